// round 2
// baseline (speedup 1.0000x reference)
#include <cuda_runtime.h>

#define KNN      11
#define NPTS     50000
#define NSP      4000
#define NBATCH   2
#define THREADS  256

// SoA site coordinates in static shared memory: 3 * 4000 * 4B = 48000 B (< 48K static limit)
__global__ __launch_bounds__(THREADS) void voronoi_knn_kernel(
    const float* __restrict__ points,    // [2, 50000, 3]
    const float* __restrict__ spoints,   // [2, 4000, 3]
    float* __restrict__ out)             // [2, 50000]
{
    __shared__ float sx[NSP];
    __shared__ float sy[NSP];
    __shared__ float sz[NSP];

    const int b = blockIdx.y;
    const float* spb = spoints + (size_t)b * NSP * 3;

    // Cooperative load of all sites for this batch into SMEM (SoA).
    for (int i = threadIdx.x; i < NSP; i += THREADS) {
        sx[i] = spb[i * 3 + 0];
        sy[i] = spb[i * 3 + 1];
        sz[i] = spb[i * 3 + 2];
    }
    __syncthreads();

    const int p = blockIdx.x * THREADS + threadIdx.x;
    if (p >= NPTS) return;

    const float* pp = points + ((size_t)b * NPTS + p) * 3;
    const float px = pp[0], py = pp[1], pz = pp[2];

    // Register-resident sorted top-K (ascending d2; stable => lower index first on ties,
    // matching jax.lax.top_k tie-break).
    float bd[KNN];
    int   bi[KNN];
#pragma unroll
    for (int k = 0; k < KNN; k++) { bd[k] = 3.4e38f; bi[k] = 0; }

#pragma unroll 4
    for (int m = 0; m < NSP; m++) {
        const float dx = px - sx[m];
        const float dy = py - sy[m];
        const float dz = pz - sz[m];
        const float d2 = fmaf(dz, dz, fmaf(dy, dy, dx * dx));
        if (d2 < bd[KNN - 1]) {
            float d = d2; int ii = m;
#pragma unroll
            for (int k = 0; k < KNN; k++) {
                if (d < bd[k]) {
                    const float td = bd[k]; bd[k] = d; d = td;
                    const int   ti = bi[k]; bi[k] = ii; ii = ti;
                }
            }
        }
    }

    // Epilogue: Voronoi edge distance using the 11 nearest sites.
    const int i0 = bi[0];
    const float cx0 = sx[i0], cy0 = sy[i0], cz0 = sz[i0];  // inside
    const float tx = px - cx0, ty = py - cy0, tz = pz - cz0;  // point_to_center

    float best = 3.4e38f;
#pragma unroll
    for (int j = 1; j < KNN; j++) {
        const int ij = bi[j];
        const float ex = sx[ij] - cx0;
        const float ey = sy[ij] - cy0;
        const float ez = sz[ij] - cz0;
        const float el2 = fmaf(ez, ez, fmaf(ey, ey, ex * ex));
        const float el  = sqrtf(el2);
        const float dp  = fmaf(tz, ez, fmaf(ty, ey, tx * ex));
        const float vl  = dp / el;
        const float t   = vl - 0.5f * el;
        best = fminf(best, t * t);
    }

    out[(size_t)b * NPTS + p] = best;
}

extern "C" void kernel_launch(void* const* d_in, const int* in_sizes, int n_in,
                              void* d_out, int out_size)
{
    const float* points  = (const float*)d_in[0];   // 2*50000*3 floats
    const float* spoints = (const float*)d_in[1];   // 2*4000*3 floats
    float* out = (float*)d_out;                     // 2*50000 floats

    dim3 grid((NPTS + THREADS - 1) / THREADS, NBATCH);
    voronoi_knn_kernel<<<grid, THREADS>>>(points, spoints, out);
}

// round 3
// speedup vs baseline: 1.0001x; 1.0001x over previous
#include <cuda_runtime.h>

#define KNN      11
#define NPTS     50000
#define NSP      4000
#define NBATCH   2
#define THREADS  256

// SoA site coordinates in static shared memory: 3 * 4000 * 4B = 48000 B (< 48K static limit)
__global__ __launch_bounds__(THREADS) void voronoi_knn_kernel(
    const float* __restrict__ points,    // [2, 50000, 3]
    const float* __restrict__ spoints,   // [2, 4000, 3]
    float* __restrict__ out)             // [2, 50000]
{
    __shared__ float sx[NSP];
    __shared__ float sy[NSP];
    __shared__ float sz[NSP];

    const int b = blockIdx.y;
    const float* spb = spoints + (size_t)b * NSP * 3;

    // Cooperative load of all sites for this batch into SMEM (SoA).
    for (int i = threadIdx.x; i < NSP; i += THREADS) {
        sx[i] = spb[i * 3 + 0];
        sy[i] = spb[i * 3 + 1];
        sz[i] = spb[i * 3 + 2];
    }
    __syncthreads();

    const int p = blockIdx.x * THREADS + threadIdx.x;
    if (p >= NPTS) return;

    const float* pp = points + ((size_t)b * NPTS + p) * 3;
    const float px = pp[0], py = pp[1], pz = pp[2];

    // Register-resident sorted top-K (ascending d2; stable => lower index first on ties,
    // matching jax.lax.top_k tie-break).
    float bd[KNN];
    int   bi[KNN];
#pragma unroll
    for (int k = 0; k < KNN; k++) { bd[k] = 3.4e38f; bi[k] = 0; }

#pragma unroll 4
    for (int m = 0; m < NSP; m++) {
        const float dx = px - sx[m];
        const float dy = py - sy[m];
        const float dz = pz - sz[m];
        const float d2 = fmaf(dz, dz, fmaf(dy, dy, dx * dx));
        if (d2 < bd[KNN - 1]) {
            float d = d2; int ii = m;
#pragma unroll
            for (int k = 0; k < KNN; k++) {
                if (d < bd[k]) {
                    const float td = bd[k]; bd[k] = d; d = td;
                    const int   ti = bi[k]; bi[k] = ii; ii = ti;
                }
            }
        }
    }

    // Epilogue: Voronoi edge distance using the 11 nearest sites.
    const int i0 = bi[0];
    const float cx0 = sx[i0], cy0 = sy[i0], cz0 = sz[i0];  // inside
    const float tx = px - cx0, ty = py - cy0, tz = pz - cz0;  // point_to_center

    float best = 3.4e38f;
#pragma unroll
    for (int j = 1; j < KNN; j++) {
        const int ij = bi[j];
        const float ex = sx[ij] - cx0;
        const float ey = sy[ij] - cy0;
        const float ez = sz[ij] - cz0;
        const float el2 = fmaf(ez, ez, fmaf(ey, ey, ex * ex));
        const float el  = sqrtf(el2);
        const float dp  = fmaf(tz, ez, fmaf(ty, ey, tx * ex));
        const float vl  = dp / el;
        const float t   = vl - 0.5f * el;
        best = fminf(best, t * t);
    }

    out[(size_t)b * NPTS + p] = best;
}

extern "C" void kernel_launch(void* const* d_in, const int* in_sizes, int n_in,
                              void* d_out, int out_size)
{
    const float* points  = (const float*)d_in[0];   // 2*50000*3 floats
    const float* spoints = (const float*)d_in[1];   // 2*4000*3 floats
    float* out = (float*)d_out;                     // 2*50000 floats

    dim3 grid((NPTS + THREADS - 1) / THREADS, NBATCH);
    voronoi_knn_kernel<<<grid, THREADS>>>(points, spoints, out);
}

// round 4
// speedup vs baseline: 1.3767x; 1.3766x over previous
#include <cuda_runtime.h>

#define KNN      11
#define NPTS     50000
#define NSP      4000
#define NB       2
#define G        20
#define NCELL    (G*G*G)          // 8000
#define TMAIN    256
#define BLKS_MAIN ((NPTS + TMAIN - 1) / TMAIN)
#define CHUNK    ((NCELL + 255) / 256)   // 32

// ---------------- device scratch (no allocations allowed) ----------------
__device__ float          g_sx[NB][NSP], g_sy[NB][NSP], g_sz[NB][NSP]; // cell-sorted sites
__device__ unsigned short g_sidx[NB][NSP];                            // original site index
__device__ unsigned short g_cst[NB][NCELL + 1];                       // cell start offsets
__device__ float          g_box[NB][9];                               // mn[3], h[3], inv_h[3]
__device__ int            g_pcnt[NB][NCELL];
__device__ int            g_pcur[NB][NCELL];
__device__ float4         g_pts[NB][NPTS];                            // cell-sorted queries (w = orig idx)

__device__ __forceinline__ int cell_of(float x, float y, float z, const float* bx) {
    int cx = (int)((x - bx[0]) * bx[6]); cx = min(G - 1, max(0, cx));
    int cy = (int)((y - bx[1]) * bx[7]); cy = min(G - 1, max(0, cy));
    int cz = (int)((z - bx[2]) * bx[8]); cz = min(G - 1, max(0, cz));
    return (cx * G + cy) * G + cz;
}

// ---------------- kernel 1: bin sites into grid (one block per batch) ----------------
static constexpr int SM_SETUP = (NCELL + NCELL + 1 + 256) * 4 + 48 * 4;

__global__ void k_setup_sites(const float* __restrict__ spoints) {
    extern __shared__ int sm[];
    int*   cnt = sm;                 // NCELL
    int*   st  = cnt + NCELL;        // NCELL+1
    int*   tot = st + NCELL + 1;     // 256
    float* red = (float*)(tot + 256); // 48
    __shared__ float sbox[9];

    const int b = blockIdx.x, tid = threadIdx.x;
    const float* sp = spoints + (size_t)b * NSP * 3;

    // zero the point-count array for this batch (used by later kernels)
    for (int c = tid; c < NCELL; c += blockDim.x) g_pcnt[b][c] = 0;

    // exact bbox of the sites
    float mnx = 3e38f, mny = 3e38f, mnz = 3e38f;
    float mxx = -3e38f, mxy = -3e38f, mxz = -3e38f;
    for (int i = tid; i < NSP; i += blockDim.x) {
        float x = sp[3*i], y = sp[3*i+1], z = sp[3*i+2];
        mnx = fminf(mnx, x); mxx = fmaxf(mxx, x);
        mny = fminf(mny, y); mxy = fmaxf(mxy, y);
        mnz = fminf(mnz, z); mxz = fmaxf(mxz, z);
    }
#pragma unroll
    for (int o = 16; o; o >>= 1) {
        mnx = fminf(mnx, __shfl_xor_sync(0xffffffffu, mnx, o));
        mny = fminf(mny, __shfl_xor_sync(0xffffffffu, mny, o));
        mnz = fminf(mnz, __shfl_xor_sync(0xffffffffu, mnz, o));
        mxx = fmaxf(mxx, __shfl_xor_sync(0xffffffffu, mxx, o));
        mxy = fmaxf(mxy, __shfl_xor_sync(0xffffffffu, mxy, o));
        mxz = fmaxf(mxz, __shfl_xor_sync(0xffffffffu, mxz, o));
    }
    int w = tid >> 5;
    if ((tid & 31) == 0) {
        red[w] = mnx; red[8 + w] = mny; red[16 + w] = mnz;
        red[24 + w] = mxx; red[32 + w] = mxy; red[40 + w] = mxz;
    }
    __syncthreads();
    if (tid == 0) {
        float a0 = red[0], a1 = red[8], a2 = red[16], a3 = red[24], a4 = red[32], a5 = red[40];
        for (int i = 1; i < 8; i++) {
            a0 = fminf(a0, red[i]);      a1 = fminf(a1, red[8 + i]);  a2 = fminf(a2, red[16 + i]);
            a3 = fmaxf(a3, red[24 + i]); a4 = fmaxf(a4, red[32 + i]); a5 = fmaxf(a5, red[40 + i]);
        }
        float hx = (a3 - a0) * (1.0f / G) * 1.000001f + 1e-30f;
        float hy = (a4 - a1) * (1.0f / G) * 1.000001f + 1e-30f;
        float hz = (a5 - a2) * (1.0f / G) * 1.000001f + 1e-30f;
        sbox[0] = a0; sbox[1] = a1; sbox[2] = a2;
        sbox[3] = hx; sbox[4] = hy; sbox[5] = hz;
        sbox[6] = 1.0f / hx; sbox[7] = 1.0f / hy; sbox[8] = 1.0f / hz;
        for (int i = 0; i < 9; i++) g_box[b][i] = sbox[i];
    }
    __syncthreads();

    // count sites per cell
    for (int c = tid; c < NCELL; c += blockDim.x) cnt[c] = 0;
    __syncthreads();
    for (int i = tid; i < NSP; i += blockDim.x) {
        int c = cell_of(sp[3*i], sp[3*i+1], sp[3*i+2], sbox);
        atomicAdd(&cnt[c], 1);
    }
    __syncthreads();

    // exclusive scan
    int c0 = tid * CHUNK, s = 0;
    for (int j = 0; j < CHUNK; j++) { int c = c0 + j; if (c < NCELL) s += cnt[c]; }
    tot[tid] = s;
    __syncthreads();
    if (tid == 0) { int run = 0; for (int i = 0; i < 256; i++) { int v = tot[i]; tot[i] = run; run += v; } }
    __syncthreads();
    int run = tot[tid];
    for (int j = 0; j < CHUNK; j++) { int c = c0 + j; if (c < NCELL) { st[c] = run; run += cnt[c]; } }
    __syncthreads();
    if (tid == 0) st[NCELL] = NSP;
    __syncthreads();

    for (int c = tid; c <= NCELL; c += blockDim.x) g_cst[b][c] = (unsigned short)st[c];
    for (int c = tid; c < NCELL; c += blockDim.x) cnt[c] = st[c];   // cnt becomes cursor
    __syncthreads();

    // scatter sites into cell-sorted order
    for (int i = tid; i < NSP; i += blockDim.x) {
        float x = sp[3*i], y = sp[3*i+1], z = sp[3*i+2];
        int c = cell_of(x, y, z, sbox);
        int pos = atomicAdd(&cnt[c], 1);
        g_sx[b][pos] = x; g_sy[b][pos] = y; g_sz[b][pos] = z;
        g_sidx[b][pos] = (unsigned short)i;
    }
}

// ---------------- kernel 2: count queries per cell ----------------
__global__ void k_count_pts(const float* __restrict__ points) {
    const int b = blockIdx.y;
    const int p = blockIdx.x * blockDim.x + threadIdx.x;
    if (p >= NPTS) return;
    const float* pp = points + ((size_t)b * NPTS + p) * 3;
    float bx[9];
#pragma unroll
    for (int i = 0; i < 9; i++) bx[i] = g_box[b][i];
    atomicAdd(&g_pcnt[b][cell_of(pp[0], pp[1], pp[2], bx)], 1);
}

// ---------------- kernel 3: scan query counts -> cursors ----------------
__global__ void k_init_cursors() {
    const int b = blockIdx.x, tid = threadIdx.x;
    __shared__ int tot[256];
    int c0 = tid * CHUNK, s = 0;
    for (int j = 0; j < CHUNK; j++) { int c = c0 + j; if (c < NCELL) s += g_pcnt[b][c]; }
    tot[tid] = s;
    __syncthreads();
    if (tid == 0) { int run = 0; for (int i = 0; i < 256; i++) { int v = tot[i]; tot[i] = run; run += v; } }
    __syncthreads();
    int run = tot[tid];
    for (int j = 0; j < CHUNK; j++) { int c = c0 + j; if (c < NCELL) { g_pcur[b][c] = run; run += g_pcnt[b][c]; } }
}

// ---------------- kernel 4: scatter queries into cell-sorted order ----------------
__global__ void k_scatter_pts(const float* __restrict__ points) {
    const int b = blockIdx.y;
    const int p = blockIdx.x * blockDim.x + threadIdx.x;
    if (p >= NPTS) return;
    const float* pp = points + ((size_t)b * NPTS + p) * 3;
    float x = pp[0], y = pp[1], z = pp[2];
    float bx[9];
#pragma unroll
    for (int i = 0; i < 9; i++) bx[i] = g_box[b][i];
    int pos = atomicAdd(&g_pcur[b][cell_of(x, y, z, bx)], 1);
    g_pts[b][pos] = make_float4(x, y, z, __int_as_float(p));
}

// ---------------- kernel 5: main — expanding-shell exact KNN + Voronoi epilogue ----------------
static constexpr int SM_MAIN = (3 * NSP + 9) * 4 + (NCELL + 1) * 2 + NSP * 2; // 72038

__global__ __launch_bounds__(TMAIN, 3) void k_main(float* __restrict__ out) {
    extern __shared__ float smf[];
    float* sx = smf;
    float* sy = sx + NSP;
    float* sz = sy + NSP;
    float* sbb = sz + NSP;                                 // 9 floats
    unsigned short* cst  = (unsigned short*)(sbb + 9);     // NCELL+1
    unsigned short* sidx = cst + (NCELL + 1);              // NSP

    const int b = blockIdx.y, tid = threadIdx.x;
    for (int i = tid; i < NSP; i += TMAIN) {
        sx[i] = g_sx[b][i]; sy[i] = g_sy[b][i]; sz[i] = g_sz[b][i];
        sidx[i] = g_sidx[b][i];
    }
    for (int i = tid; i <= NCELL; i += TMAIN) cst[i] = g_cst[b][i];
    if (tid < 9) sbb[tid] = g_box[b][tid];
    __syncthreads();

    const int t = blockIdx.x * TMAIN + tid;
    if (t >= NPTS) return;

    const float4 P = g_pts[b][t];
    const float px = P.x, py = P.y, pz = P.z;
    const int orig = __float_as_int(P.w);

    const float mnx = sbb[0], mny = sbb[1], mnz = sbb[2];
    const float hx = sbb[3], hy = sbb[4], hz = sbb[5];
    int cx = (int)((px - mnx) * sbb[6]); cx = min(G - 1, max(0, cx));
    int cy = (int)((py - mny) * sbb[7]); cy = min(G - 1, max(0, cy));
    int cz = (int)((pz - mnz) * sbb[8]); cz = min(G - 1, max(0, cz));

    float bd[KNN];
    int   bo[KNN];   // key = (orig_site_idx << 12) | sorted_pos  — lex order == jax tie-break
#pragma unroll
    for (int k = 0; k < KNN; k++) { bd[k] = 3.4e38f; bo[k] = 0x7FFFFFFF; }

    auto visit = [&](int X, int Y, int Z) {
        int c = (X * G + Y) * G + Z;
        int m1 = cst[c + 1];
        for (int m = cst[c]; m < m1; m++) {
            float dx = px - sx[m], dy = py - sy[m], dz = pz - sz[m];
            float d2 = fmaf(dz, dz, fmaf(dy, dy, dx * dx));
            if (d2 <= bd[KNN - 1]) {
                float d = d2;
                int kk = ((int)sidx[m] << 12) | m;
#pragma unroll
                for (int k = 0; k < KNN; k++) {
                    bool sw = (d < bd[k]) || ((d == bd[k]) && (kk < bo[k]));
                    if (sw) {
                        float td = bd[k]; bd[k] = d;  d = td;
                        int   ti = bo[k]; bo[k] = kk; kk = ti;
                    }
                }
            }
        }
    };

    for (int r = 0; r < G; r++) {
        const int zlo = max(cz - r, 0), zhi = min(cz + r, G - 1);
        const int ylo = max(cy - r, 0), yhi = min(cy + r, G - 1);
        const int xlo = max(cx - r, 0), xhi = min(cx + r, G - 1);
        for (int Z = zlo; Z <= zhi; Z++) {
            const bool zb = (Z == cz - r) || (Z == cz + r);
            for (int Y = ylo; Y <= yhi; Y++) {
                if (zb || (Y == cy - r) || (Y == cy + r)) {
                    for (int X = xlo; X <= xhi; X++) visit(X, Y, Z);
                } else {
                    int X = cx - r; if (X >= 0)     visit(X, Y, Z);
                    X = cx + r;     if (X <= G - 1) visit(X, Y, Z);
                }
            }
        }
        // completeness: everything scanned?
        if (xlo == 0 && xhi == G - 1 && ylo == 0 && yhi == G - 1 && zlo == 0 && zhi == G - 1) break;
        // ring bound: all unexplored sites strictly farther than current 11th (with fp slack)
        if (bd[KNN - 1] < 3.0e38f) {
            float bnd = 3.0e38f;
            if (cx - r > 0)     bnd = fminf(bnd, px - (mnx + (float)(cx - r) * hx));
            if (cx + r < G - 1) bnd = fminf(bnd, (mnx + (float)(cx + r + 1) * hx) - px);
            if (cy - r > 0)     bnd = fminf(bnd, py - (mny + (float)(cy - r) * hy));
            if (cy + r < G - 1) bnd = fminf(bnd, (mny + (float)(cy + r + 1) * hy) - py);
            if (cz - r > 0)     bnd = fminf(bnd, pz - (mnz + (float)(cz - r) * hz));
            if (cz + r < G - 1) bnd = fminf(bnd, (mnz + (float)(cz + r + 1) * hz) - pz);
            if (bnd > 0.0f && bnd * bnd >= bd[KNN - 1] * 1.0002f) break;
        }
    }

    // Voronoi-edge epilogue on the 11 selected sites (order of slots 1..10 irrelevant: min)
    const int p0 = bo[0] & 4095;
    const float cx0 = sx[p0], cy0 = sy[p0], cz0 = sz[p0];
    const float tx = px - cx0, ty = py - cy0, tz = pz - cz0;
    float best = 3.4e38f;
#pragma unroll
    for (int j = 1; j < KNN; j++) {
        const int pj = bo[j] & 4095;
        const float ex = sx[pj] - cx0, ey = sy[pj] - cy0, ez = sz[pj] - cz0;
        const float el2 = fmaf(ez, ez, fmaf(ey, ey, ex * ex));
        const float dp  = fmaf(tz, ez, fmaf(ty, ey, tx * ex));
        const float tt  = fmaf(-0.5f, el2, dp) * rsqrtf(el2);  // (dp - el2/2)/sqrt(el2)
        best = fminf(best, tt * tt);
    }
    out[(size_t)b * NPTS + orig] = best;
}

// ---------------- launch ----------------
extern "C" void kernel_launch(void* const* d_in, const int* in_sizes, int n_in,
                              void* d_out, int out_size)
{
    const float* points  = (const float*)d_in[0];
    const float* spoints = (const float*)d_in[1];
    float* out = (float*)d_out;

    cudaFuncSetAttribute(k_setup_sites, cudaFuncAttributeMaxDynamicSharedMemorySize, SM_SETUP);
    cudaFuncSetAttribute(k_main,        cudaFuncAttributeMaxDynamicSharedMemorySize, SM_MAIN);

    k_setup_sites<<<NB, 256, SM_SETUP>>>(spoints);
    dim3 gp((NPTS + 255) / 256, NB);
    k_count_pts<<<gp, 256>>>(points);
    k_init_cursors<<<NB, 256>>>();
    k_scatter_pts<<<gp, 256>>>(points);
    k_main<<<dim3(BLKS_MAIN, NB), TMAIN, SM_MAIN>>>(out);
}